// round 1
// baseline (speedup 1.0000x reference)
#include <cuda_runtime.h>

#define NN 50000
#define EE 850000

// ---------------- scratch (device globals; no allocation allowed) ----------
__device__ float    g_feat[NN * 128];   // per-layer transformed features (max H*D=128)
__device__ float    g_h0[NN * 128];     // layer0 output
__device__ float    g_h1[NN * 64];      // layer1 output
__device__ float    g_el[NN * 2];
__device__ float    g_er[NN * 2];
__device__ float    g_e[EE * 2];        // per-(edge,head) score -> exp value
__device__ unsigned g_m[NN * 2];        // encoded segment max
__device__ float    g_s[NN * 2];        // segment sum
__device__ int      g_src[EE];
__device__ int      g_dst[EE];
__device__ int      g_is64;

// order-preserving float<->uint encoding for atomicMax
__device__ __forceinline__ unsigned fenc(float f) {
    unsigned u = __float_as_uint(f);
    return u ^ ((unsigned)((int)u >> 31) | 0x80000000u);
}
__device__ __forceinline__ float fdec(unsigned u) {
    u = u ^ ((u & 0x80000000u) ? 0x80000000u : 0xFFFFFFFFu);
    return __uint_as_float(u);
}

// ---------------- index width detection + conversion -----------------------
__global__ void detect_kernel(const unsigned* src_w, const unsigned* dst_w) {
    // int64 little-endian node ids (< 2^31) => all odd words zero
    int i64 = 1;
    for (int k = 0; k < 16; k++) {
        if (src_w[2 * k + 1] != 0u) i64 = 0;
        if (dst_w[2 * k + 1] != 0u) i64 = 0;
    }
    g_is64 = i64;
}

__global__ void convert_kernel(const void* src, const void* dst) {
    int i = blockIdx.x * blockDim.x + threadIdx.x;
    if (i >= EE) return;
    if (g_is64) {
        g_src[i] = (int)((const long long*)src)[i];
        g_dst[i] = (int)((const long long*)dst)[i];
    } else {
        g_src[i] = ((const int*)src)[i];
        g_dst[i] = ((const int*)dst)[i];
    }
}

// ---------------- GEMM + attention projections ------------------------------
// One warp per node. Lane l (l < HD/4) computes output columns [4l, 4l+3]
// via float4 loads of W. x row cached in 4 regs/lane, broadcast by shfl.
__global__ void gemm_feat_kernel(const float* __restrict__ x,
                                 const float* __restrict__ W,
                                 const float* __restrict__ al,
                                 const float* __restrict__ ar,
                                 float* __restrict__ feat,
                                 float* __restrict__ el,
                                 float* __restrict__ er,
                                 int Fin, int H, int D) {
    int gwarp = (blockIdx.x * blockDim.x + threadIdx.x) >> 5;
    int lane  = threadIdx.x & 31;
    if (gwarp >= NN) return;
    int HD  = H * D;
    int HD4 = HD >> 2;
    bool active = lane < HD4;

    const float* xrow = x + (size_t)gwarp * Fin;
    float xr[4];
#pragma unroll
    for (int w = 0; w < 4; w++) {
        int k = lane + 32 * w;
        xr[w] = (k < Fin) ? xrow[k] : 0.0f;
    }

    float a0 = 0.f, a1 = 0.f, a2 = 0.f, a3 = 0.f;
    const float4* W4 = (const float4*)W;
    for (int w = 0; w < 4; w++) {
        if (32 * w >= Fin) break;
        float xw = xr[w];
#pragma unroll
        for (int kk = 0; kk < 32; kk++) {
            float xk = __shfl_sync(0xFFFFFFFFu, xw, kk);
            if (active) {
                float4 wv = __ldg(&W4[(32 * w + kk) * HD4 + lane]);
                a0 += xk * wv.x; a1 += xk * wv.y;
                a2 += xk * wv.z; a3 += xk * wv.w;
            }
        }
    }

    float pl = 0.f, pr = 0.f;
    if (active) {
        ((float4*)(feat + (size_t)gwarp * HD))[lane] = make_float4(a0, a1, a2, a3);
        int c  = 4 * lane;
        int h  = c / D;
        int d0 = c - h * D;
        const float* alh = al + h * D + d0;
        const float* arh = ar + h * D + d0;
        pl = a0 * alh[0] + a1 * alh[1] + a2 * alh[2] + a3 * alh[3];
        pr = a0 * arh[0] + a1 * arh[1] + a2 * arh[2] + a3 * arh[3];
    }
    if (H == 2) {
        // lanes 0-15 head0, 16-31 head1
#pragma unroll
        for (int off = 8; off; off >>= 1) {
            pl += __shfl_xor_sync(0xFFFFFFFFu, pl, off);
            pr += __shfl_xor_sync(0xFFFFFFFFu, pr, off);
        }
        if (lane == 0 || lane == 16) {
            int h = lane >> 4;
            el[gwarp * 2 + h] = pl;
            er[gwarp * 2 + h] = pr;
        }
    } else {
#pragma unroll
        for (int off = 16; off; off >>= 1) {
            pl += __shfl_xor_sync(0xFFFFFFFFu, pl, off);
            pr += __shfl_xor_sync(0xFFFFFFFFu, pr, off);
        }
        if (lane == 0) { el[gwarp] = pl; er[gwarp] = pr; }
    }
}

// ---------------- init: out = bias, m = -inf(enc 0), s = 0 ------------------
__global__ void init_kernel(float* __restrict__ out, const float* __restrict__ b,
                            int HD, int H) {
    int i = blockIdx.x * blockDim.x + threadIdx.x;
    if (i < NN * HD) out[i] = b[i % HD];
    if (i < NN * H) { g_m[i] = 0u; g_s[i] = 0.f; }
}

// ---------------- edge pass 1: score + segment max --------------------------
__global__ void edge_score_kernel(const float* __restrict__ el,
                                  const float* __restrict__ er, int H) {
    int t = blockIdx.x * blockDim.x + threadIdx.x;
    if (t >= EE * H) return;
    int i = (H == 2) ? (t >> 1) : t;
    int h = (H == 2) ? (t & 1) : 0;
    int s = g_src[i], d = g_dst[i];
    float v = el[s * H + h] + er[d * H + h];
    v = v > 0.f ? v : 0.2f * v;
    g_e[t] = v;
    atomicMax(&g_m[d * H + h], fenc(v));
}

// ---------------- edge pass 2: exp + segment sum ----------------------------
__global__ void edge_exp_kernel(int H) {
    int t = blockIdx.x * blockDim.x + threadIdx.x;
    if (t >= EE * H) return;
    int i = (H == 2) ? (t >> 1) : t;
    int h = (H == 2) ? (t & 1) : 0;
    int d = g_dst[i];
    float mm = fdec(g_m[d * H + h]);
    float ee = __expf(g_e[t] - mm);
    g_e[t] = ee;
    atomicAdd(&g_s[d * H + h], ee);
}

// ---------------- edge pass 3: weighted aggregate (warp per edge-head) ------
__global__ void edge_aggr_kernel(const float* __restrict__ feat,
                                 float* __restrict__ out, int H, int D) {
    int gw   = (blockIdx.x * blockDim.x + threadIdx.x) >> 5;
    int lane = threadIdx.x & 31;
    if (gw >= EE * H) return;
    int i = (H == 2) ? (gw >> 1) : gw;
    int h = (H == 2) ? (gw & 1) : 0;
    int s = g_src[i], d = g_dst[i];
    float alpha = g_e[gw] / g_s[d * H + h];
    int HD = H * D, D4 = D >> 2;
    if (lane < D4) {
        float4 f = ((const float4*)(feat + (size_t)s * HD + h * D))[lane];
        float4 v = make_float4(f.x * alpha, f.y * alpha, f.z * alpha, f.w * alpha);
        atomicAdd(((float4*)(out + (size_t)d * HD + h * D)) + lane, v);
    }
}

// ---------------- host-side layer driver ------------------------------------
static void run_layer(const float* x, const float* W, const float* al,
                      const float* ar, const float* b, float* out,
                      float* feat_p, float* el_p, float* er_p,
                      int Fin, int H, int D) {
    int HD = H * D;
    gemm_feat_kernel<<<(NN + 7) / 8, 256>>>(x, W, al, ar, feat_p, el_p, er_p, Fin, H, D);
    int ninit = NN * HD;
    init_kernel<<<(ninit + 255) / 256, 256>>>(out, b, HD, H);
    int nt = EE * H;
    edge_score_kernel<<<(nt + 255) / 256, 256>>>(el_p, er_p, H);
    edge_exp_kernel<<<(nt + 255) / 256, 256>>>(H);
    long long aggr_threads = (long long)nt * 32;
    edge_aggr_kernel<<<(int)((aggr_threads + 255) / 256), 256>>>(feat_p, out, H, D);
}

extern "C" void kernel_launch(void* const* d_in, const int* in_sizes, int n_in,
                              void* d_out, int out_size) {
    const float* in_feat = (const float*)d_in[0];
    const void*  src     = d_in[1];
    const void*  dst     = d_in[2];
    const float* W0 = (const float*)d_in[3];
    const float* al0 = (const float*)d_in[4];
    const float* ar0 = (const float*)d_in[5];
    const float* b0 = (const float*)d_in[6];
    const float* W1 = (const float*)d_in[7];
    const float* al1 = (const float*)d_in[8];
    const float* ar1 = (const float*)d_in[9];
    const float* b1 = (const float*)d_in[10];
    const float* W2 = (const float*)d_in[11];
    const float* al2 = (const float*)d_in[12];
    const float* ar2 = (const float*)d_in[13];
    const float* b2 = (const float*)d_in[14];
    float* out = (float*)d_out;

    // resolve device-global scratch addresses (host funcs can't take &__device__)
    float *feat_p, *h0_p, *h1_p, *el_p, *er_p;
    cudaGetSymbolAddress((void**)&feat_p, g_feat);
    cudaGetSymbolAddress((void**)&h0_p, g_h0);
    cudaGetSymbolAddress((void**)&h1_p, g_h1);
    cudaGetSymbolAddress((void**)&el_p, g_el);
    cudaGetSymbolAddress((void**)&er_p, g_er);

    detect_kernel<<<1, 1>>>((const unsigned*)src, (const unsigned*)dst);
    convert_kernel<<<(EE + 255) / 256, 256>>>(src, dst);

    // layer 0: 128 -> 2 heads x 64, output flatten -> [N,128]
    run_layer(in_feat, W0, al0, ar0, b0, h0_p, feat_p, el_p, er_p, 128, 2, 64);
    // layer 1: 128 -> 1 head x 64 (mean over 1 head = identity) -> [N,64]
    run_layer(h0_p, W1, al1, ar1, b1, h1_p, feat_p, el_p, er_p, 128, 1, 64);
    // layer 2: 64 -> 1 head x 40 -> [N,40] straight into d_out
    run_layer(h1_p, W2, al2, ar2, b2, out, feat_p, el_p, er_p, 64, 1, 40);
}

// round 2
// speedup vs baseline: 1.6627x; 1.6627x over previous
#include <cuda_runtime.h>
#include <math_constants.h>

#define NN 50000
#define EE 850000

// ---------------- scratch (device globals; no allocation allowed) ----------
__device__ float g_feat[NN * 128];   // per-layer transformed features (max H*D=128)
__device__ float g_h0[NN * 128];     // layer0 output
__device__ float g_h1[NN * 64];      // layer1 output
__device__ float g_el[NN * 2];
__device__ float g_er[NN * 2];
__device__ int   g_src[EE];
__device__ int   g_dst[EE];
__device__ int   g_count[NN];
__device__ int   g_cursor[NN];
__device__ int   g_rowptr[NN + 1];
__device__ int   g_colsrc[EE];
__device__ int   g_is64;

// ---------------- index width detection ------------------------------------
__global__ void detect_kernel(const unsigned* src_w, const unsigned* dst_w) {
    // int64 little-endian node ids (< 2^31) => all odd 32-bit words zero
    int i64 = 1;
    for (int k = 0; k < 16; k++) {
        if (src_w[2 * k + 1] != 0u) i64 = 0;
        if (dst_w[2 * k + 1] != 0u) i64 = 0;
    }
    g_is64 = i64;
}

__global__ void zero_count_kernel() {
    int i = blockIdx.x * blockDim.x + threadIdx.x;
    if (i < NN) g_count[i] = 0;
}

// convert indices + histogram of dst
__global__ void hist_kernel(const void* src, const void* dst) {
    int i = blockIdx.x * blockDim.x + threadIdx.x;
    if (i >= EE) return;
    int s, d;
    if (g_is64) {
        s = (int)((const long long*)src)[i];
        d = (int)((const long long*)dst)[i];
    } else {
        s = ((const int*)src)[i];
        d = ((const int*)dst)[i];
    }
    g_src[i] = s;
    g_dst[i] = d;
    atomicAdd(&g_count[d], 1);
}

// single-block exclusive scan over g_count -> g_rowptr, g_cursor
__global__ void scan_kernel() {
    __shared__ int sh[1024];
    __shared__ int carry;
    if (threadIdx.x == 0) carry = 0;
    __syncthreads();
    for (int base = 0; base < NN; base += 1024) {
        int i = base + threadIdx.x;
        int v = (i < NN) ? g_count[i] : 0;
        sh[threadIdx.x] = v;
        __syncthreads();
#pragma unroll
        for (int off = 1; off < 1024; off <<= 1) {
            int t = (threadIdx.x >= off) ? sh[threadIdx.x - off] : 0;
            __syncthreads();
            sh[threadIdx.x] += t;
            __syncthreads();
        }
        int excl = sh[threadIdx.x] - v + carry;
        if (i < NN) { g_rowptr[i] = excl; g_cursor[i] = excl; }
        __syncthreads();
        if (threadIdx.x == 1023) carry += sh[1023];
        __syncthreads();
    }
    if (threadIdx.x == 0) g_rowptr[NN] = carry;
}

__global__ void scatter_kernel() {
    int i = blockIdx.x * blockDim.x + threadIdx.x;
    if (i >= EE) return;
    int d = g_dst[i];
    int pos = atomicAdd(&g_cursor[d], 1);
    g_colsrc[pos] = g_src[i];
}

// ---------------- GEMM + attention projections ------------------------------
// One warp per node. Lane l (l < HD/4) computes output columns [4l, 4l+3].
__global__ void gemm_feat_kernel(const float* __restrict__ x,
                                 const float* __restrict__ W,
                                 const float* __restrict__ al,
                                 const float* __restrict__ ar,
                                 float* __restrict__ feat,
                                 float* __restrict__ el,
                                 float* __restrict__ er,
                                 int Fin, int H, int D) {
    int gwarp = (blockIdx.x * blockDim.x + threadIdx.x) >> 5;
    int lane  = threadIdx.x & 31;
    if (gwarp >= NN) return;
    int HD  = H * D;
    int HD4 = HD >> 2;
    bool active = lane < HD4;

    const float* xrow = x + (size_t)gwarp * Fin;
    float xr[4];
#pragma unroll
    for (int w = 0; w < 4; w++) {
        int k = lane + 32 * w;
        xr[w] = (k < Fin) ? xrow[k] : 0.0f;
    }

    float a0 = 0.f, a1 = 0.f, a2 = 0.f, a3 = 0.f;
    const float4* W4 = (const float4*)W;
    for (int w = 0; w < 4; w++) {
        if (32 * w >= Fin) break;
        float xw = xr[w];
#pragma unroll
        for (int kk = 0; kk < 32; kk++) {
            float xk = __shfl_sync(0xFFFFFFFFu, xw, kk);
            if (active) {
                float4 wv = __ldg(&W4[(32 * w + kk) * HD4 + lane]);
                a0 += xk * wv.x; a1 += xk * wv.y;
                a2 += xk * wv.z; a3 += xk * wv.w;
            }
        }
    }

    float pl = 0.f, pr = 0.f;
    if (active) {
        ((float4*)(feat + (size_t)gwarp * HD))[lane] = make_float4(a0, a1, a2, a3);
        int c  = 4 * lane;
        int h  = c / D;
        int d0 = c - h * D;
        const float* alh = al + h * D + d0;
        const float* arh = ar + h * D + d0;
        pl = a0 * alh[0] + a1 * alh[1] + a2 * alh[2] + a3 * alh[3];
        pr = a0 * arh[0] + a1 * arh[1] + a2 * arh[2] + a3 * arh[3];
    }
    if (H == 2) {
#pragma unroll
        for (int off = 8; off; off >>= 1) {
            pl += __shfl_xor_sync(0xFFFFFFFFu, pl, off);
            pr += __shfl_xor_sync(0xFFFFFFFFu, pr, off);
        }
        if (lane == 0 || lane == 16) {
            int h = lane >> 4;
            el[gwarp * 2 + h] = pl;
            er[gwarp * 2 + h] = pr;
        }
    } else {
#pragma unroll
        for (int off = 16; off; off >>= 1) {
            pl += __shfl_xor_sync(0xFFFFFFFFu, pl, off);
            pr += __shfl_xor_sync(0xFFFFFFFFu, pr, off);
        }
        if (lane == 0) { el[gwarp] = pl; er[gwarp] = pr; }
    }
}

// ---------------- fused online-softmax aggregation ---------------------------
// GPW node-groups per warp; each group has HD/4 lanes, lane sub covers
// feature columns [4*sub, 4*sub+3] of its node. One pass over in-edges with
// the online-softmax recurrence; zero atomics; bias fused into the store.
template <int H, int D, int GPW>
__global__ void aggr_kernel(const float* __restrict__ feat,
                            const float* __restrict__ el,
                            const float* __restrict__ er,
                            const float* __restrict__ bias,
                            float* __restrict__ out) {
    constexpr int HD  = H * D;
    constexpr int HD4 = HD / 4;
    int warp = (blockIdx.x * blockDim.x + threadIdx.x) >> 5;
    int lane = threadIdx.x & 31;
    int g    = lane / HD4;
    int sub  = lane - g * HD4;
    int node = warp * GPW + g;
    if (g >= GPW || node >= NN) return;

    const int h    = (4 * sub) / D;
    const float er_d = __ldg(&er[node * H + h]);
    const int e0 = g_rowptr[node];
    const int e1 = g_rowptr[node + 1];

    float m = -CUDART_INF_F, ssum = 0.f;
    float ax = 0.f, ay = 0.f, az = 0.f, aw = 0.f;

    for (int e = e0; e < e1; e++) {
        int s = __ldg(&g_colsrc[e]);
        float v = __ldg(&el[s * H + h]) + er_d;
        v = v > 0.f ? v : 0.2f * v;
        float nm = fmaxf(m, v);
        float scale = __expf(m - nm);   // first iter: exp(-inf) = 0
        float p     = __expf(v - nm);
        float4 f = __ldg((const float4*)(feat + (size_t)s * HD + 4 * sub));
        ax = ax * scale + p * f.x;
        ay = ay * scale + p * f.y;
        az = az * scale + p * f.z;
        aw = aw * scale + p * f.w;
        ssum = ssum * scale + p;
        m = nm;
    }

    float inv = __frcp_rn(ssum);
    float4 o;
    o.x = ax * inv + __ldg(&bias[4 * sub + 0]);
    o.y = ay * inv + __ldg(&bias[4 * sub + 1]);
    o.z = az * inv + __ldg(&bias[4 * sub + 2]);
    o.w = aw * inv + __ldg(&bias[4 * sub + 3]);
    *(float4*)(out + (size_t)node * HD + 4 * sub) = o;
}

// ---------------- host-side drivers -----------------------------------------
static void run_gemm(const float* x, const float* W, const float* al,
                     const float* ar, float* feat_p, float* el_p, float* er_p,
                     int Fin, int H, int D) {
    gemm_feat_kernel<<<(NN + 7) / 8, 256>>>(x, W, al, ar, feat_p, el_p, er_p, Fin, H, D);
}

extern "C" void kernel_launch(void* const* d_in, const int* in_sizes, int n_in,
                              void* d_out, int out_size) {
    const float* in_feat = (const float*)d_in[0];
    const void*  src     = d_in[1];
    const void*  dst     = d_in[2];
    const float* W0 = (const float*)d_in[3];
    const float* al0 = (const float*)d_in[4];
    const float* ar0 = (const float*)d_in[5];
    const float* b0 = (const float*)d_in[6];
    const float* W1 = (const float*)d_in[7];
    const float* al1 = (const float*)d_in[8];
    const float* ar1 = (const float*)d_in[9];
    const float* b1 = (const float*)d_in[10];
    const float* W2 = (const float*)d_in[11];
    const float* al2 = (const float*)d_in[12];
    const float* ar2 = (const float*)d_in[13];
    const float* b2 = (const float*)d_in[14];
    float* out = (float*)d_out;

    float *feat_p, *h0_p, *h1_p, *el_p, *er_p;
    cudaGetSymbolAddress((void**)&feat_p, g_feat);
    cudaGetSymbolAddress((void**)&h0_p, g_h0);
    cudaGetSymbolAddress((void**)&h1_p, g_h1);
    cudaGetSymbolAddress((void**)&el_p, g_el);
    cudaGetSymbolAddress((void**)&er_p, g_er);

    // ---- build CSR (by dst) once; reused by all 3 layers ----
    detect_kernel<<<1, 1>>>((const unsigned*)src, (const unsigned*)dst);
    zero_count_kernel<<<(NN + 255) / 256, 256>>>();
    hist_kernel<<<(EE + 255) / 256, 256>>>(src, dst);
    scan_kernel<<<1, 1024>>>();
    scatter_kernel<<<(EE + 255) / 256, 256>>>();

    // ---- layer 0: 128 -> 2 heads x 64, flatten -> [N,128] ----
    run_gemm(in_feat, W0, al0, ar0, feat_p, el_p, er_p, 128, 2, 64);
    aggr_kernel<2, 64, 1><<<(NN * 32 + 255) / 256, 256>>>(feat_p, el_p, er_p, b0, h0_p);

    // ---- layer 1: 128 -> 1 head x 64 (mean over 1 head = identity) ----
    run_gemm(h0_p, W1, al1, ar1, feat_p, el_p, er_p, 128, 1, 64);
    {
        int warps = (NN + 1) / 2;
        aggr_kernel<1, 64, 2><<<(warps * 32 + 255) / 256, 256>>>(feat_p, el_p, er_p, b1, h1_p);
    }

    // ---- layer 2: 64 -> 1 head x 40 -> [N,40] into d_out ----
    run_gemm(h1_p, W2, al2, ar2, feat_p, el_p, er_p, 64, 1, 40);
    {
        int warps = (NN + 2) / 3;
        aggr_kernel<1, 40, 3><<<(warps * 32 + 255) / 256, 256>>>(feat_p, el_p, er_p, b2, out);
    }
}

// round 3
// speedup vs baseline: 2.7190x; 1.6353x over previous
#include <cuda_runtime.h>
#include <math_constants.h>

#define NN 50000
#define EE 850000

// ---------------- scratch (device globals; no allocation allowed) ----------
__device__ float g_feat[NN * 128];
__device__ float g_h0[NN * 128];
__device__ float g_h1[NN * 64];
__device__ float g_el[NN * 2];
__device__ float g_er[NN * 2];
__device__ int   g_src[EE];
__device__ int   g_dst[EE];
__device__ int   g_count[NN];
__device__ int   g_cursor[NN];
__device__ int   g_rowptr[NN + 1];
__device__ int   g_colsrc[EE];
__device__ int   g_bsum[64];
__device__ int   g_is64;

// ---------------- index width detection ------------------------------------
__global__ void detect_kernel(const unsigned* src_w, const unsigned* dst_w) {
    int i64 = 1;
    for (int k = 0; k < 16; k++) {
        if (src_w[2 * k + 1] != 0u) i64 = 0;
        if (dst_w[2 * k + 1] != 0u) i64 = 0;
    }
    g_is64 = i64;
}

__global__ void zero_count_kernel() {
    int i = blockIdx.x * blockDim.x + threadIdx.x;
    if (i < NN) g_count[i] = 0;
}

// convert indices + histogram of dst
__global__ void hist_kernel(const void* src, const void* dst) {
    int i = blockIdx.x * blockDim.x + threadIdx.x;
    if (i >= EE) return;
    int s, d;
    if (g_is64) {
        s = (int)((const long long*)src)[i];
        d = (int)((const long long*)dst)[i];
    } else {
        s = ((const int*)src)[i];
        d = ((const int*)dst)[i];
    }
    g_src[i] = s;
    g_dst[i] = d;
    atomicAdd(&g_count[d], 1);
}

// ---------------- fast 3-phase exclusive scan -------------------------------
// phase 1: per-block (1024) scan via warp shuffles; block-local exclusive to
//          g_cursor, block totals to g_bsum
__global__ void scan_block_kernel() {
    __shared__ int wsum[32];
    int i = blockIdx.x * 1024 + threadIdx.x;
    int lane = threadIdx.x & 31, wid = threadIdx.x >> 5;
    int v = (i < NN) ? g_count[i] : 0;
    int incl = v;
#pragma unroll
    for (int off = 1; off < 32; off <<= 1) {
        int t = __shfl_up_sync(0xFFFFFFFFu, incl, off);
        if (lane >= off) incl += t;
    }
    if (lane == 31) wsum[wid] = incl;
    __syncthreads();
    if (wid == 0) {
        int s = wsum[lane];
        int si = s;
#pragma unroll
        for (int off = 1; off < 32; off <<= 1) {
            int t = __shfl_up_sync(0xFFFFFFFFu, si, off);
            if (lane >= off) si += t;
        }
        wsum[lane] = si - s;  // exclusive warp prefix
        if (lane == 31) g_bsum[blockIdx.x] = si;
    }
    __syncthreads();
    if (i < NN) g_cursor[i] = incl - v + wsum[wid];
}

// phase 2: one warp scans the (<=64) block sums, in place, exclusive
__global__ void scan_sums_kernel(int nb) {
    int lane = threadIdx.x;
    int va = (lane < nb) ? g_bsum[lane] : 0;
    int vb = (32 + lane < nb) ? g_bsum[32 + lane] : 0;
    int a = va, b = vb;
#pragma unroll
    for (int off = 1; off < 32; off <<= 1) {
        int t = __shfl_up_sync(0xFFFFFFFFu, a, off);
        if (lane >= off) a += t;
        int u = __shfl_up_sync(0xFFFFFFFFu, b, off);
        if (lane >= off) b += u;
    }
    int totA = __shfl_sync(0xFFFFFFFFu, a, 31);
    if (lane < nb) g_bsum[lane] = a - va;
    if (32 + lane < nb) g_bsum[32 + lane] = totA + b - vb;
}

// phase 3: add block offsets -> rowptr + cursor
__global__ void scan_add_kernel() {
    int i = blockIdx.x * blockDim.x + threadIdx.x;
    if (i < NN) {
        int r = g_cursor[i] + g_bsum[i >> 10];
        g_rowptr[i] = r;
        g_cursor[i] = r;
    }
    if (i == 0) g_rowptr[NN] = EE;
}

__global__ void scatter_kernel() {
    int i = blockIdx.x * blockDim.x + threadIdx.x;
    if (i >= EE) return;
    int d = g_dst[i];
    int pos = atomicAdd(&g_cursor[d], 1);
    g_colsrc[pos] = g_src[i];
}

// ---------------- tiled GEMM (smem W + x, register micro-tiles) -------------
// threads = TX*TY (256). Block covers TM*TY nodes x HD cols (TN=4 per thread).
template <int FIN, int HD, int TM, int TX, int TY>
__global__ void gemm_tiled_kernel(const float* __restrict__ x,
                                  const float* __restrict__ W,
                                  float* __restrict__ feat) {
    constexpr int NODES = TM * TY;
    extern __shared__ float sh[];
    float* Wsh = sh;                 // [FIN][HD]
    float* Xsh = sh + FIN * HD;      // [NODES][FIN]
    int node0 = blockIdx.x * NODES;
    int tid = threadIdx.x;

    for (int i = tid; i < FIN * HD / 4; i += TX * TY)
        ((float4*)Wsh)[i] = ((const float4*)W)[i];
    for (int i = tid; i < NODES * FIN / 4; i += TX * TY) {
        int n = i / (FIN / 4), k4 = i % (FIN / 4);
        int gn = node0 + n;
        ((float4*)Xsh)[i] = (gn < NN) ? ((const float4*)(x + (size_t)gn * FIN))[k4]
                                      : make_float4(0.f, 0.f, 0.f, 0.f);
    }
    __syncthreads();

    int tx = tid % TX, ty = tid / TX;
    float ac[TM][4];
#pragma unroll
    for (int m = 0; m < TM; m++)
#pragma unroll
        for (int n = 0; n < 4; n++) ac[m][n] = 0.f;

#pragma unroll 4
    for (int k = 0; k < FIN; k++) {
        float4 wv = ((float4*)(Wsh + k * HD))[tx];
#pragma unroll
        for (int m = 0; m < TM; m++) {
            float xv = Xsh[(ty * TM + m) * FIN + k];
            ac[m][0] += xv * wv.x;
            ac[m][1] += xv * wv.y;
            ac[m][2] += xv * wv.z;
            ac[m][3] += xv * wv.w;
        }
    }
#pragma unroll
    for (int m = 0; m < TM; m++) {
        int node = node0 + ty * TM + m;
        if (node < NN)
            ((float4*)(feat + (size_t)node * HD))[tx] =
                make_float4(ac[m][0], ac[m][1], ac[m][2], ac[m][3]);
    }
}

// ---------------- el/er projections (warp per node) --------------------------
__global__ void elr_kernel(const float* __restrict__ feat,
                           const float* __restrict__ al,
                           const float* __restrict__ ar,
                           float* __restrict__ el, float* __restrict__ er,
                           int H, int D) {
    int warp = (blockIdx.x * blockDim.x + threadIdx.x) >> 5;
    int lane = threadIdx.x & 31;
    if (warp >= NN) return;
    int HD = H * D, HD4 = HD >> 2;
    float pl = 0.f, pr = 0.f;
    if (lane < HD4) {
        float4 f = __ldg((const float4*)(feat + (size_t)warp * HD) + lane);
        int c = 4 * lane, h = c / D, d0 = c - h * D;
        const float* alh = al + h * D + d0;
        const float* arh = ar + h * D + d0;
        pl = f.x * alh[0] + f.y * alh[1] + f.z * alh[2] + f.w * alh[3];
        pr = f.x * arh[0] + f.y * arh[1] + f.z * arh[2] + f.w * arh[3];
    }
    if (H == 2) {
#pragma unroll
        for (int off = 8; off; off >>= 1) {
            pl += __shfl_xor_sync(0xFFFFFFFFu, pl, off);
            pr += __shfl_xor_sync(0xFFFFFFFFu, pr, off);
        }
        if (lane == 0 || lane == 16) {
            int h = lane >> 4;
            el[warp * 2 + h] = pl;
            er[warp * 2 + h] = pr;
        }
    } else {
#pragma unroll
        for (int off = 16; off; off >>= 1) {
            pl += __shfl_xor_sync(0xFFFFFFFFu, pl, off);
            pr += __shfl_xor_sync(0xFFFFFFFFu, pr, off);
        }
        if (lane == 0) { el[warp] = pl; er[warp] = pr; }
    }
}

// ---------------- small fused GEMM (layer 2 only: Fin=64, HD=40) -------------
__global__ void gemm_feat_kernel(const float* __restrict__ x,
                                 const float* __restrict__ W,
                                 const float* __restrict__ al,
                                 const float* __restrict__ ar,
                                 float* __restrict__ feat,
                                 float* __restrict__ el,
                                 float* __restrict__ er,
                                 int Fin, int H, int D) {
    int gwarp = (blockIdx.x * blockDim.x + threadIdx.x) >> 5;
    int lane  = threadIdx.x & 31;
    if (gwarp >= NN) return;
    int HD  = H * D;
    int HD4 = HD >> 2;
    bool active = lane < HD4;

    const float* xrow = x + (size_t)gwarp * Fin;
    float xr[4];
#pragma unroll
    for (int w = 0; w < 4; w++) {
        int k = lane + 32 * w;
        xr[w] = (k < Fin) ? xrow[k] : 0.0f;
    }

    float a0 = 0.f, a1 = 0.f, a2 = 0.f, a3 = 0.f;
    const float4* W4 = (const float4*)W;
    for (int w = 0; w < 4; w++) {
        if (32 * w >= Fin) break;
        float xw = xr[w];
#pragma unroll
        for (int kk = 0; kk < 32; kk++) {
            float xk = __shfl_sync(0xFFFFFFFFu, xw, kk);
            if (active) {
                float4 wv = __ldg(&W4[(32 * w + kk) * HD4 + lane]);
                a0 += xk * wv.x; a1 += xk * wv.y;
                a2 += xk * wv.z; a3 += xk * wv.w;
            }
        }
    }

    float pl = 0.f, pr = 0.f;
    if (active) {
        ((float4*)(feat + (size_t)gwarp * HD))[lane] = make_float4(a0, a1, a2, a3);
        int c  = 4 * lane;
        int h  = c / D;
        int d0 = c - h * D;
        const float* alh = al + h * D + d0;
        const float* arh = ar + h * D + d0;
        pl = a0 * alh[0] + a1 * alh[1] + a2 * alh[2] + a3 * alh[3];
        pr = a0 * arh[0] + a1 * arh[1] + a2 * arh[2] + a3 * arh[3];
    }
#pragma unroll
    for (int off = 16; off; off >>= 1) {
        pl += __shfl_xor_sync(0xFFFFFFFFu, pl, off);
        pr += __shfl_xor_sync(0xFFFFFFFFu, pr, off);
    }
    if (lane == 0) { el[gwarp] = pl; er[gwarp] = pr; }
}

// ---------------- fused online-softmax aggregation ---------------------------
template <int H, int D, int GPW>
__global__ void aggr_kernel(const float* __restrict__ feat,
                            const float* __restrict__ el,
                            const float* __restrict__ er,
                            const float* __restrict__ bias,
                            float* __restrict__ out) {
    constexpr int HD  = H * D;
    constexpr int HD4 = HD / 4;
    int warp = (blockIdx.x * blockDim.x + threadIdx.x) >> 5;
    int lane = threadIdx.x & 31;
    int g    = lane / HD4;
    int sub  = lane - g * HD4;
    int node = warp * GPW + g;
    if (g >= GPW || node >= NN) return;

    const int h    = (4 * sub) / D;
    const float er_d = __ldg(&er[node * H + h]);
    const int e0 = g_rowptr[node];
    const int e1 = g_rowptr[node + 1];

    float m = -CUDART_INF_F, ssum = 0.f;
    float ax = 0.f, ay = 0.f, az = 0.f, aw = 0.f;

    for (int e = e0; e < e1; e++) {
        int s = __ldg(&g_colsrc[e]);
        float v = __ldg(&el[s * H + h]) + er_d;
        v = v > 0.f ? v : 0.2f * v;
        float nm = fmaxf(m, v);
        float scale = __expf(m - nm);
        float p     = __expf(v - nm);
        float4 f = __ldg((const float4*)(feat + (size_t)s * HD + 4 * sub));
        ax = ax * scale + p * f.x;
        ay = ay * scale + p * f.y;
        az = az * scale + p * f.z;
        aw = aw * scale + p * f.w;
        ssum = ssum * scale + p;
        m = nm;
    }

    float inv = __frcp_rn(ssum);
    float4 o;
    o.x = ax * inv + __ldg(&bias[4 * sub + 0]);
    o.y = ay * inv + __ldg(&bias[4 * sub + 1]);
    o.z = az * inv + __ldg(&bias[4 * sub + 2]);
    o.w = aw * inv + __ldg(&bias[4 * sub + 3]);
    *(float4*)(out + (size_t)node * HD + 4 * sub) = o;
}

// ---------------- launcher ---------------------------------------------------
extern "C" void kernel_launch(void* const* d_in, const int* in_sizes, int n_in,
                              void* d_out, int out_size) {
    const float* in_feat = (const float*)d_in[0];
    const void*  src     = d_in[1];
    const void*  dst     = d_in[2];
    const float* W0 = (const float*)d_in[3];
    const float* al0 = (const float*)d_in[4];
    const float* ar0 = (const float*)d_in[5];
    const float* b0 = (const float*)d_in[6];
    const float* W1 = (const float*)d_in[7];
    const float* al1 = (const float*)d_in[8];
    const float* ar1 = (const float*)d_in[9];
    const float* b1 = (const float*)d_in[10];
    const float* W2 = (const float*)d_in[11];
    const float* al2 = (const float*)d_in[12];
    const float* ar2 = (const float*)d_in[13];
    const float* b2 = (const float*)d_in[14];
    float* out = (float*)d_out;

    float *feat_p, *h0_p, *h1_p, *el_p, *er_p;
    cudaGetSymbolAddress((void**)&feat_p, g_feat);
    cudaGetSymbolAddress((void**)&h0_p, g_h0);
    cudaGetSymbolAddress((void**)&h1_p, g_h1);
    cudaGetSymbolAddress((void**)&el_p, g_el);
    cudaGetSymbolAddress((void**)&er_p, g_er);

    // opt-in dynamic smem for the tiled GEMMs
    constexpr int SMEM_L0 = (128 * 128 + 64 * 128) * 4;  // 96 KB
    constexpr int SMEM_L1 = (128 * 64 + 64 * 128) * 4;   // 64 KB
    cudaFuncSetAttribute(gemm_tiled_kernel<128, 128, 8, 32, 8>,
                         cudaFuncAttributeMaxDynamicSharedMemorySize, SMEM_L0);
    cudaFuncSetAttribute(gemm_tiled_kernel<128, 64, 4, 16, 16>,
                         cudaFuncAttributeMaxDynamicSharedMemorySize, SMEM_L1);

    // ---- build CSR (by dst) once; reused by all 3 layers ----
    detect_kernel<<<1, 1>>>((const unsigned*)src, (const unsigned*)dst);
    zero_count_kernel<<<(NN + 255) / 256, 256>>>();
    hist_kernel<<<(EE + 255) / 256, 256>>>(src, dst);
    int nb = (NN + 1023) / 1024;
    scan_block_kernel<<<nb, 1024>>>();
    scan_sums_kernel<<<1, 32>>>(nb);
    scan_add_kernel<<<(NN + 255) / 256, 256>>>();
    scatter_kernel<<<(EE + 255) / 256, 256>>>();

    // ---- layer 0: 128 -> 2 heads x 64 ----
    gemm_tiled_kernel<128, 128, 8, 32, 8>
        <<<(NN + 63) / 64, 256, SMEM_L0>>>(in_feat, W0, feat_p);
    elr_kernel<<<(NN + 7) / 8, 256>>>(feat_p, al0, ar0, el_p, er_p, 2, 64);
    aggr_kernel<2, 64, 1><<<(NN * 32 + 255) / 256, 256>>>(feat_p, el_p, er_p, b0, h0_p);

    // ---- layer 1: 128 -> 1 head x 64 ----
    gemm_tiled_kernel<128, 64, 4, 16, 16>
        <<<(NN + 63) / 64, 256, SMEM_L1>>>(h0_p, W1, feat_p);
    elr_kernel<<<(NN + 7) / 8, 256>>>(feat_p, al1, ar1, el_p, er_p, 1, 64);
    {
        int warps = (NN + 1) / 2;
        aggr_kernel<1, 64, 2><<<(warps * 32 + 255) / 256, 256>>>(feat_p, el_p, er_p, b1, h1_p);
    }

    // ---- layer 2: 64 -> 1 head x 40 -> d_out ----
    gemm_feat_kernel<<<(NN + 7) / 8, 256>>>(h1_p, W2, al2, ar2, feat_p, el_p, er_p, 64, 1, 40);
    {
        int warps = (NN + 2) / 3;
        aggr_kernel<1, 40, 3><<<(warps * 32 + 255) / 256, 256>>>(feat_p, el_p, er_p, b2, out);
    }
}